// round 17
// baseline (speedup 1.0000x reference)
#include <cuda_runtime.h>
#include <cuda_fp16.h>
#include <cstdint>
#include <math.h>

#define BB 4
#define SS 1024
#define DD 1024
#define HH 16
#define DH 64
#define GM_M (BB*SS)   // 4096

// Q pre-scale: 0.125 * log2(e); QK MMA then yields log2-domain scores.
#define QSCALE 0.18033688011112042f

// ---------------------------------------------------------------------------
// Device scratch (fp16 single-precision operands)
// ---------------------------------------------------------------------------
__device__ __half g_Xh[3][GM_M * DD];
__device__ __half g_Wth[3][DD * DD];
__device__ __half g_Qh[BB * HH * SS * DH];    // pre-scaled by QSCALE
__device__ __half g_Kh[BB * HH * SS * DH];
__device__ __half g_Vth[BB * HH * DH * SS];   // [bh][d][s]

// ---------------------------------------------------------------------------
// Helpers
// ---------------------------------------------------------------------------
__device__ __forceinline__ uint32_t smem_u32(const void* p) {
    uint32_t a;
    asm("{ .reg .u64 t; cvta.to.shared.u64 t, %1; cvt.u32.u64 %0, t; }" : "=r"(a) : "l"(p));
    return a;
}
#define LDSM_X4(r0, r1, r2, r3, addr) \
    asm volatile("ldmatrix.sync.aligned.m8n8.x4.shared.b16 {%0,%1,%2,%3}, [%4];" \
        : "=r"(r0), "=r"(r1), "=r"(r2), "=r"(r3) : "r"(addr))
#define MMA16816(d, a, b) \
    asm volatile("mma.sync.aligned.m16n8k16.row.col.f32.f16.f16.f32 " \
        "{%0,%1,%2,%3}, {%4,%5,%6,%7}, {%8,%9}, {%0,%1,%2,%3};" \
        : "+f"((d)[0]), "+f"((d)[1]), "+f"((d)[2]), "+f"((d)[3]) \
        : "r"((a)[0]), "r"((a)[1]), "r"((a)[2]), "r"((a)[3]), \
          "r"((b)[0]), "r"((b)[1]))
__device__ __forceinline__ void cp16(uint32_t saddr, const void* g) {
    asm volatile("cp.async.cg.shared.global [%0], [%1], 16;" :: "r"(saddr), "l"(g));
}
#define CP_COMMIT() asm volatile("cp.async.commit_group;" ::: "memory")
#define CP_WAIT(n)  asm volatile("cp.async.wait_group %0;" :: "n"(n) : "memory")

__device__ __forceinline__ uint32_t pack_h2(float a, float b) {
    __half2 h = __floats2half2_rn(a, b);
    return *reinterpret_cast<uint32_t*>(&h);
}
__device__ __forceinline__ float ex2(float x) {
    float r;
    asm("ex2.approx.f32 %0, %1;" : "=f"(r) : "f"(x));
    return r;
}

// ---------------------------------------------------------------------------
// Kernel: merged conversions (unchanged).
// ---------------------------------------------------------------------------
__global__ __launch_bounds__(256) void conv_merged_kernel(
    const float4* __restrict__ q, const float4* __restrict__ k,
    const float4* __restrict__ v,
    const float* __restrict__ Wq, const float* __restrict__ Wk,
    const float* __restrict__ Wv)
{
    __shared__ float tile[32][33];
    const int bid = blockIdx.x;
    const int tid = threadIdx.x;

    if (bid < 1536) {
        int z = bid / 512;
        int blk = bid - z * 512;
        const float4* src = (z == 0) ? q : (z == 1) ? k : v;
        uint32_t* dst = reinterpret_cast<uint32_t*>(g_Xh[z]);
        const int n4 = GM_M * DD / 4;
        for (int i = blk * 256 + tid; i < n4; i += 512 * 256) {
            float4 f = src[i];
            dst[2*i]   = pack_h2(f.x, f.y);
            dst[2*i+1] = pack_h2(f.z, f.w);
        }
    } else {
        int w = bid - 1536;
        int z = w >> 10;
        int rem = w & 1023;
        const float* W = (z == 0) ? Wq : (z == 1) ? Wk : Wv;
        __half* Wh = g_Wth[z];
        int bx = (rem & 31) * 32;
        int by = (rem >> 5) * 32;
        int tx = tid & 31;
        int ty = tid >> 5;

        #pragma unroll
        for (int r = 0; r < 4; ++r) {
            int kk = by + ty + r * 8;
            tile[ty + r * 8][tx] = W[(size_t)kk * DD + bx + tx];
        }
        __syncthreads();
        #pragma unroll
        for (int r = 0; r < 4; ++r) {
            int n = bx + ty + r * 8;
            int kk = by + tx;
            Wh[(size_t)n * DD + kk] = __float2half(tile[tx][ty + r * 8]);
        }
    }
}

// ---------------------------------------------------------------------------
// Kernel: fp16 HMMA projection GEMM (unchanged).
// ---------------------------------------------------------------------------
#define PROJ_STAGE_BYTES 36864
#define PROJ_SMEM_BYTES  (2 * PROJ_STAGE_BYTES)

__global__ __launch_bounds__(256, 2) void proj_mma_kernel(
    const float* __restrict__ bq, const float* __restrict__ bk,
    const float* __restrict__ bv)
{
    extern __shared__ char smc[];
    const uint32_t smb = smem_u32(smc);
    const int tid  = threadIdx.x;
    const int lane = tid & 31;
    const int wid  = tid >> 5;
    const int wm   = wid & 3;
    const int wn   = wid >> 2;
    const int z  = blockIdx.z;
    const int n0 = blockIdx.x * 128;
    const int m0 = blockIdx.y * 128;

    const __half* Xh = g_Xh[z];
    const __half* Wh = g_Wth[z];
    const float* bias = (z == 0) ? bq : (z == 1) ? bk : bv;

    float acc[2][8][4];
    #pragma unroll
    for (int f = 0; f < 2; ++f)
        #pragma unroll
        for (int j = 0; j < 8; ++j)
            #pragma unroll
            for (int c = 0; c < 4; ++c) acc[f][j][c] = 0.0f;

    {
        #pragma unroll
        for (int t = 0; t < 4; ++t) {
            int idx = tid + t * 256;
            int row = idx >> 3, seg = idx & 7;
            uint32_t so = (uint32_t)(row * 144 + seg * 16);
            cp16(smb +         so, Xh + (size_t)(m0 + row) * DD + seg * 8);
            cp16(smb + 18432 + so, Wh + (size_t)(n0 + row) * DD + seg * 8);
        }
        CP_COMMIT();
    }

    const uint32_t a_off =
        (uint32_t)((wm * 32 + (lane & 15)) * 144 + (lane >> 4) * 16);
    const int bg = lane >> 3;
    const uint32_t b_off =
        (uint32_t)((wn * 64 + (bg >> 1) * 8 + (lane & 7)) * 144 + (bg & 1) * 16);

    for (int i = 0; i < 16; ++i) {
        CP_WAIT(0);
        __syncthreads();
        if (i < 15) {
            const int k0 = (i + 1) * 64;
            uint32_t sb = smb + ((i + 1) & 1) * PROJ_STAGE_BYTES;
            #pragma unroll
            for (int t = 0; t < 4; ++t) {
                int idx = tid + t * 256;
                int row = idx >> 3, seg = idx & 7;
                uint32_t so = (uint32_t)(row * 144 + seg * 16);
                cp16(sb +         so, Xh + (size_t)(m0 + row) * DD + k0 + seg * 8);
                cp16(sb + 18432 + so, Wh + (size_t)(n0 + row) * DD + k0 + seg * 8);
            }
            CP_COMMIT();
        }

        const uint32_t sb = smb + (i & 1) * PROJ_STAGE_BYTES;
        #pragma unroll
        for (int s = 0; s < 4; ++s) {
            const uint32_t ks = (uint32_t)(s * 32);
            uint32_t ah[2][4];
            #pragma unroll
            for (int f = 0; f < 2; ++f) {
                uint32_t aaddr = sb + a_off + (uint32_t)(f * 16 * 144) + ks;
                LDSM_X4(ah[f][0], ah[f][1], ah[f][2], ah[f][3], aaddr);
            }
            uint32_t bh[4][4];
            #pragma unroll
            for (int nf = 0; nf < 4; ++nf) {
                uint32_t baddr = sb + 18432 + b_off + (uint32_t)(nf * 16 * 144) + ks;
                LDSM_X4(bh[nf][0], bh[nf][1], bh[nf][2], bh[nf][3], baddr);
            }
            #pragma unroll
            for (int f = 0; f < 2; ++f) {
                #pragma unroll
                for (int j = 0; j < 8; ++j) {
                    uint32_t bfh[2] = { bh[j >> 1][(j & 1) * 2], bh[j >> 1][(j & 1) * 2 + 1] };
                    MMA16816(acc[f][j], ah[f], bfh);
                }
            }
        }
    }

    const int er = m0 + wm * 32 + (lane >> 2);
    const int ec = n0 + wn * 64 + (lane & 3) * 2;
    float breg[8][2];
    #pragma unroll
    for (int j = 0; j < 8; ++j) {
        breg[j][0] = __ldg(bias + ec + j * 8);
        breg[j][1] = __ldg(bias + ec + j * 8 + 1);
    }

    if (z == 0) {
        #pragma unroll
        for (int f = 0; f < 2; ++f) {
            #pragma unroll
            for (int j = 0; j < 8; ++j) {
                int col = ec + j * 8;
                int hh = col >> 6, d = col & 63;
                #pragma unroll
                for (int rr = 0; rr < 2; ++rr) {
                    int row = er + f * 16 + rr * 8;
                    int bb = row >> 10, s = row & 1023;
                    float v0 = (acc[f][j][rr * 2 + 0] + breg[j][0]) * QSCALE;
                    float v1 = (acc[f][j][rr * 2 + 1] + breg[j][1]) * QSCALE;
                    size_t o = (((size_t)(bb * HH + hh)) * SS + s) * DH + d;
                    *(uint32_t*)(g_Qh + o) = pack_h2(v0, v1);
                }
            }
        }
    } else if (z == 1) {
        #pragma unroll
        for (int f = 0; f < 2; ++f) {
            #pragma unroll
            for (int j = 0; j < 8; ++j) {
                int col = ec + j * 8;
                int hh = col >> 6, d = col & 63;
                #pragma unroll
                for (int rr = 0; rr < 2; ++rr) {
                    int row = er + f * 16 + rr * 8;
                    int bb = row >> 10, s = row & 1023;
                    float v0 = acc[f][j][rr * 2 + 0] + breg[j][0];
                    float v1 = acc[f][j][rr * 2 + 1] + breg[j][1];
                    size_t o = (((size_t)(bb * HH + hh)) * SS + s) * DH + d;
                    *(uint32_t*)(g_Kh + o) = pack_h2(v0, v1);
                }
            }
        }
    } else {
        #pragma unroll
        for (int f = 0; f < 2; ++f) {
            #pragma unroll
            for (int j = 0; j < 8; ++j) {
                int col = ec + j * 8;
                int hh = col >> 6, d = col & 63;
                #pragma unroll
                for (int rr = 0; rr < 2; ++rr) {
                    int row = er + f * 16 + rr * 8;
                    int bb = row >> 10, s = row & 1023;
                    size_t base = (size_t)(bb * HH + hh) * DH * SS;
                    g_Vth[base + (size_t)d * SS + s] =
                        __float2half(acc[f][j][rr * 2 + 0] + breg[j][0]);
                    g_Vth[base + (size_t)(d + 1) * SS + s] =
                        __float2half(acc[f][j][rr * 2 + 1] + breg[j][1]);
                }
            }
        }
    }
}

// ---------------------------------------------------------------------------
// Kernel: attention, 64 q-rows / CTA, 512 threads / 16 warps, occupancy 1.
// 256-wide K/V chunks (4 iterations per phase).  16 warps give 4 warps/SMSP
// of latency hiding.  V chunk 0 pre-issued during last QK iteration.
// Q pre-scaled -> bare EX2; fp16-pair score storage; attn write fused.
// ---------------------------------------------------------------------------
#define QR       64
#define SUSTR    516
#define AT_SU    0                        // 64*516*4 = 132096
#define AT_QOFF  132096                   // 64*144 = 9216
#define AT_STG   141312                   // 2*36864 = 73728
#define AT_BUF   36864                    // K: 256*144; V: 64*528 (33792)
#define AT_SUMS  215040                   // 64 floats
#define AT_INVS  215296                   // 64 floats
#define AT_SMEM  215552

__global__ __launch_bounds__(512, 1) void attn_mma_kernel(
    float* __restrict__ ctx, float* __restrict__ attn)
{
    extern __shared__ char smc[];
    uint32_t* Su  = (uint32_t*)(smc + AT_SU);
    float* sums = (float*)(smc + AT_SUMS);
    float* invs = (float*)(smc + AT_INVS);
    const uint32_t smb = smem_u32(smc);
    const int tid = threadIdx.x, lane = tid & 31, wid = tid >> 5;   // wid 0..15
    const int q0 = blockIdx.x * QR;
    const int h  = blockIdx.y;
    const int b  = blockIdx.z;
    const int bh = b * HH + h;

    // ---- Q tiles (64 rows x 144B) into padded smem; zero row sums ----
    if (tid < 512) {
        int row = tid >> 3, seg = tid & 7;
        size_t g = ((size_t)bh * SS + q0 + row) * DH + seg * 8;
        *(uint4*)(smc + AT_QOFF + row * 144 + seg * 16) = *(const uint4*)(g_Qh + g);
    }
    if (tid < 64) sums[tid] = 0.0f;

    const __half* Kh = g_Kh + (size_t)bh * SS * DH;
    const __half* Vh = g_Vth + (size_t)bh * DH * SS;

    // ---- issue K chunk 0 (256 rows x 144B) ----
    {
        uint32_t sb = smb + AT_STG;
        #pragma unroll
        for (int t = 0; t < 4; ++t) {
            int idx = tid + t * 512;
            int row = idx >> 3, seg = idx & 7;
            cp16(sb + row * 144 + seg * 16, Kh + (size_t)row * DH + seg * 8);
        }
        CP_COMMIT();
    }
    __syncthreads();

    // ---- hoist Q fragments: warp rows wm*16..+15 ----
    const int wm = wid & 3, wn = wid >> 2;    // wm 0..3 rows, wn 0..3 64-col group
    const int bg = lane >> 3;
    uint32_t qf[4][4];
    #pragma unroll
    for (int ks = 0; ks < 4; ++ks) {
        uint32_t aaddr = smb + AT_QOFF + (wm * 16 + (lane & 15)) * 144
                       + (lane >> 4) * 16 + ks * 32;
        LDSM_X4(qf[ks][0], qf[ks][1], qf[ks][2], qf[ks][3], aaddr);
    }

    // ---- QK (log2-domain) + EX2 + fp16 pack: 4 chunks of 256 keys ----
    float sumA = 0.0f, sumB = 0.0f;
    const int r_ = wm * 16 + (lane >> 2);
    for (int ic = 0; ic < 4; ++ic) {
        CP_WAIT(0);
        __syncthreads();
        if (ic < 3) {
            uint32_t sb = smb + AT_STG + ((ic + 1) & 1) * AT_BUF;
            const __half* kh = Kh + (size_t)(ic + 1) * 256 * DH;
            #pragma unroll
            for (int t = 0; t < 4; ++t) {
                int idx = tid + t * 512;
                int row = idx >> 3, seg = idx & 7;
                cp16(sb + row * 144 + seg * 16, kh + (size_t)row * DH + seg * 8);
            }
            CP_COMMIT();
        } else {
            // pre-issue V chunk 0 into buffer 0 (free after ic=2 compute)
            uint32_t sb = smb + AT_STG;
            #pragma unroll
            for (int t = 0; t < 4; ++t) {
                int idx = tid + t * 512;
                int row = idx >> 5, seg = idx & 31;
                cp16(sb + row * 528 + seg * 16, Vh + (size_t)row * SS + seg * 8);
            }
            CP_COMMIT();
        }

        uint32_t sb = smb + AT_STG + (ic & 1) * AT_BUF;
        float acc[8][4];
        #pragma unroll
        for (int jj = 0; jj < 8; ++jj)
            #pragma unroll
            for (int c = 0; c < 4; ++c) acc[jj][c] = 0.0f;

        #pragma unroll
        for (int ks = 0; ks < 4; ++ks) {
            #pragma unroll
            for (int gg = 0; gg < 4; ++gg) {
                uint32_t bhf[4];
                uint32_t baddr = sb + (wn * 64 + gg * 16 + (bg >> 1) * 8 + (lane & 7)) * 144
                               + (bg & 1) * 16 + ks * 32;
                LDSM_X4(bhf[0], bhf[1], bhf[2], bhf[3], baddr);
                #pragma unroll
                for (int j2 = 0; j2 < 2; ++j2) {
                    uint32_t b2h[2] = { bhf[j2 * 2], bhf[j2 * 2 + 1] };
                    MMA16816(acc[gg * 2 + j2], qf[ks], b2h);
                }
            }
        }
        #pragma unroll
        for (int jj = 0; jj < 8; ++jj) {
            int pc = ic * 128 + wn * 32 + (jj >> 1) * 8 + (jj & 1) * 4 + (lane & 3);
            float e0 = ex2(acc[jj][0]);
            float e1 = ex2(acc[jj][1]);
            float e2 = ex2(acc[jj][2]);
            float e3 = ex2(acc[jj][3]);
            sumA += e0 + e1;
            sumB += e2 + e3;
            Su[r_ * SUSTR + pc]       = pack_h2(e0, e1);
            Su[(r_ + 8) * SUSTR + pc] = pack_h2(e2, e3);
        }
    }

    // ---- reduce row sums (4 lanes per row within warp, 4 warps per row) ----
    sumA += __shfl_xor_sync(0xffffffffu, sumA, 1);
    sumA += __shfl_xor_sync(0xffffffffu, sumA, 2);
    sumB += __shfl_xor_sync(0xffffffffu, sumB, 1);
    sumB += __shfl_xor_sync(0xffffffffu, sumB, 2);
    if ((lane & 3) == 0) {
        atomicAdd(&sums[r_], sumA);
        atomicAdd(&sums[r_ + 8], sumB);
    }
    __syncthreads();   // sums complete; Su writes ordered
    if (tid < 64) invs[tid] = 1.0f / sums[tid];
    __syncthreads();   // invs visible

    // ---- P @ V: 4 chunks of 256 cols; warp owns 16x16 output; write fused --
    const int wm2 = wid & 3, wn2 = wid >> 2;
    float acc2[2][4];
    #pragma unroll
    for (int j2 = 0; j2 < 2; ++j2)
        #pragma unroll
        for (int c = 0; c < 4; ++c) acc2[j2][c] = 0.0f;

    const int ar = wm2 * 16 + (lane >> 2);
    float* const attn_base = attn + ((size_t)(h * BB + b)) * SS * SS + (size_t)q0 * SS;

    for (int jc = 0; jc < 4; ++jc) {
        CP_WAIT(0);
        __syncthreads();
        if (jc < 3) {
            uint32_t sb = smb + AT_STG + ((jc + 1) & 1) * AT_BUF;
            const __half* vh = Vh + (size_t)(jc + 1) * 256;
            #pragma unroll
            for (int t = 0; t < 4; ++t) {
                int idx = tid + t * 512;
                int row = idx >> 5, seg = idx & 31;
                cp16(sb + row * 528 + seg * 16, vh + (size_t)row * SS + seg * 8);
            }
            CP_COMMIT();
        }

        uint32_t sb = smb + AT_STG + (jc & 1) * AT_BUF;
        #pragma unroll
        for (int ks = 0; ks < 16; ++ks) {
            uint32_t bhf[4];
            uint32_t baddr = sb + (wn2 * 16 + (bg >> 1) * 8 + (lane & 7)) * 528
                           + (bg & 1) * 16 + ks * 32;
            LDSM_X4(bhf[0], bhf[1], bhf[2], bhf[3], baddr);
            int pc = jc * 128 + ks * 8 + (lane & 3);
            uint32_t ah[4];
            ah[0] = Su[ar * SUSTR + pc];
            ah[1] = Su[(ar + 8) * SUSTR + pc];
            ah[2] = Su[ar * SUSTR + pc + 4];
            ah[3] = Su[(ar + 8) * SUSTR + pc + 4];
            #pragma unroll
            for (int j2 = 0; j2 < 2; ++j2) {
                uint32_t b2h[2] = { bhf[j2 * 2], bhf[j2 * 2 + 1] };
                MMA16816(acc2[j2], ah, b2h);
            }
        }

        // fused attn write for chunk jc: warp wid writes rows 4*wid..4*wid+3,
        // cols jc*256..jc*256+255 (two float4 per lane per row)
        #pragma unroll
        for (int rr = 0; rr < 4; ++rr) {
            const int row = wid * 4 + rr;
            const float inv = invs[row];
            const uint2* spp = (const uint2*)(Su + row * SUSTR);
            float4* arow4 = (float4*)(attn_base + (size_t)row * SS);
            #pragma unroll
            for (int c = 0; c < 2; ++c) {
                uint2 p = spp[jc * 64 + c * 32 + lane];
                __half2 ha = *reinterpret_cast<__half2*>(&p.x);
                __half2 hb = *reinterpret_cast<__half2*>(&p.y);
                float4 av = { __low2float(ha) * inv, __high2float(ha) * inv,
                              __low2float(hb) * inv, __high2float(hb) * inv };
                arow4[jc * 64 + c * 32 + lane] = av;
            }
        }
    }

    // ---- context epilogue ----
    {
        const float inv0 = invs[ar];
        const float inv1 = invs[ar + 8];
        #pragma unroll
        for (int j2 = 0; j2 < 2; ++j2) {
            int c = h * 64 + wn2 * 16 + j2 * 8 + (lane & 3) * 2;
            float2 v0 = { acc2[j2][0] * inv0, acc2[j2][1] * inv0 };
            float2 v1 = { acc2[j2][2] * inv1, acc2[j2][3] * inv1 };
            *(float2*)&ctx[((size_t)b * SS + q0 + ar) * DD + c]     = v0;
            *(float2*)&ctx[((size_t)b * SS + q0 + ar + 8) * DD + c] = v1;
        }
    }
}

// ---------------------------------------------------------------------------
extern "C" void kernel_launch(void* const* d_in, const int* in_sizes, int n_in,
                              void* d_out, int out_size)
{
    const float* query = (const float*)d_in[0];
    const float* key   = (const float*)d_in[1];
    const float* value = (const float*)d_in[2];
    const float* Wq    = (const float*)d_in[3];
    const float* bq    = (const float*)d_in[4];
    const float* Wk    = (const float*)d_in[5];
    const float* bk    = (const float*)d_in[6];
    const float* Wv    = (const float*)d_in[7];
    const float* bv    = (const float*)d_in[8];

    float* out  = (float*)d_out;
    float* ctx  = out;
    float* attn = out + (size_t)BB * SS * DD;

    conv_merged_kernel<<<4608, 256>>>(
        (const float4*)query, (const float4*)key, (const float4*)value,
        Wq, Wk, Wv);

    cudaFuncSetAttribute(proj_mma_kernel, cudaFuncAttributeMaxDynamicSharedMemorySize,
                         PROJ_SMEM_BYTES);
    proj_mma_kernel<<<dim3(8, 32, 3), 256, PROJ_SMEM_BYTES>>>(bq, bk, bv);

    cudaFuncSetAttribute(attn_mma_kernel, cudaFuncAttributeMaxDynamicSharedMemorySize,
                         AT_SMEM);
    attn_mma_kernel<<<dim3(SS / QR, HH, BB), 512, AT_SMEM>>>(ctx, attn);
}